// round 12
// baseline (speedup 1.0000x reference)
#include <cuda_runtime.h>
#include <cuda_bf16.h>

#define NG      1024
#define NCHUNK  8
#define CHUNK   (NG / NCHUNK)          // 128
#define IMG_W   256
#define IMG_H   256
#define NPIX    (IMG_W * IMG_H)
#define TILE_W  16
#define TILE_H  16
#define NTX     (IMG_W / TILE_W)       // 16
#define NTY     (IMG_H / TILE_H)       // 16
#define NTILE   (NTX * NTY)            // 256
#define QMAX    10.0f                  // bbox truncation: missed alpha <= op*e^-5

// Preprocessed gaussian tables (SoA)
__device__ float2 pPos[NG];            // mx, my
__device__ float4 pA[NG];              // A, B, C, D   (q-hat polynomial coeffs)
__device__ float4 pB[NG];              // E, F, rx, ry (F has log2(op) folded in)
// Per-pixel partial composites, interleaved [pixel][chunk]: (acc,T) pairs.
__device__ float2 g_part[NPIX * NCHUNK];
// Per-tile arrival counters (zero at load; combiner resets each run).
__device__ int g_cnt[NTILE];

__device__ __forceinline__ float fast_sigmoid(float x) {
    return 1.0f / (1.0f + __expf(-x));
}
__device__ __forceinline__ float ex2(float x) {
    float y; asm("ex2.approx.ftz.f32 %0, %1;" : "=f"(y) : "f"(x)); return y;
}

__global__ void __launch_bounds__(64) prep_kernel(
        const float* __restrict__ means,
        const float* __restrict__ scales,
        const float* __restrict__ thetas,
        const float* __restrict__ opacities) {
    const int i = blockIdx.x * 64 + threadIdx.x;

    float mx = means[2 * i + 0];
    float my = means[2 * i + 1];
    {   // tanh(x) = 1 - 2/(e^{2x}+1)
        float ex = __expf(2.0f * mx);
        mx = 1.0f - 2.0f / (ex + 1.0f);
        float ey = __expf(2.0f * my);
        my = 1.0f - 2.0f / (ey + 1.0f);
    }
    float s0 = __expf(scales[2 * i + 0]);
    float s1 = __expf(scales[2 * i + 1]);
    float th = fast_sigmoid(thetas[i]) * 6.283185307179586f;
    float op = fast_sigmoid(opacities[i]);

    float si, c;
    __sincosf(th, &si, &c);
    float s02 = s0 * s0, s12 = s1 * s1;
    const float J = 1e-6f;
    float a = c * c * s02 + si * si * s12 + J;   // Sigma_00
    float b = c * si * (s02 - s12);              // Sigma_01
    float d = si * si * s02 + c * c * s12 + J;   // Sigma_11
    float inv = 1.0f / (a * d - b * b);
    const float S = -0.7213475204444817f;        // -0.5 * log2(e)
    float A =  d * inv * S;
    float B = -b * inv * (2.0f * S);
    float C =  a * inv * S;
    float D = -(2.0f * A * mx + B * my);
    float E = -(B * mx + 2.0f * C * my);
    float F = A * mx * mx + B * mx * my + C * my * my + __log2f(op);

    pPos[i] = make_float2(mx, my);
    pA[i]   = make_float4(A, B, C, D);
    pB[i]   = make_float4(E, F, sqrtf(QMAX * a), sqrtf(QMAX * d));
}

// Block (16,8) = 128 threads; tile 16x16, each thread owns (x,y) and (x,y+8h).
__global__ void __launch_bounds__(128) render_kernel(float* __restrict__ out) {
    __shared__ float4 sA[CHUNK];       // A, B, C, D
    __shared__ float2 sEF[CHUNK];      // E, F
    __shared__ int warp_cnt[4];
    __shared__ int warp_off[4];
    __shared__ int s_total;
    __shared__ int s_last;

    const int tid  = threadIdx.y * 16 + threadIdx.x;
    const int warp = tid >> 5;
    const int lane = tid & 31;
    const float h = 2.0f / 255.0f;

    // ---- Cull this chunk's 128 gaussians (one per thread) + compaction ----
    {
        const int gi = blockIdx.z * CHUNK + tid;
        float2 pos = pPos[gi];
        float4 efr = pB[gi];
        const float cx     = -1.0f + ((float)(blockIdx.x * TILE_W) + 7.5f) * h;
        const float cy     = -1.0f + ((float)(blockIdx.y * TILE_H) + 7.5f) * h;
        const float half_t = 7.5f * h;
        bool pass = (fabsf(pos.x - cx) < efr.z + half_t) &&
                    (fabsf(pos.y - cy) < efr.w + half_t);

        unsigned bal = __ballot_sync(0xffffffffu, pass);
        int pre = __popc(bal & ((1u << lane) - 1u));
        if (lane == 0) warp_cnt[warp] = __popc(bal);
        __syncthreads();
        if (tid == 0) {
            int s = 0;
            #pragma unroll
            for (int w = 0; w < 4; ++w) { warp_off[w] = s; s += warp_cnt[w]; }
            s_total = s;
        }
        __syncthreads();
        if (pass) {
            int slot = warp_off[warp] + pre;
            sA[slot]  = pA[gi];
            sEF[slot] = make_float2(efr.x, efr.y);
        }
    }
    __syncthreads();
    const int cnt = s_total;

    // ---- Two pixels per thread: (x, y) and (x, y+8 rows) ----
    const int px  = blockIdx.x * TILE_W + threadIdx.x;
    const int py0 = blockIdx.y * TILE_H + threadIdx.y;
    const float x  = -1.0f + (float)px * h;
    const float y0 = -1.0f + (float)py0 * h;
    const float y1 = y0 + 8.0f * h;

    float acc0 = 0.0f, T0 = 1.0f;
    float acc1 = 0.0f, T1 = 1.0f;

    #pragma unroll 2
    for (int i = 0; i < cnt; ++i) {
        float4 p = sA[i];
        float2 e = sEF[i];
        float hx = fmaf(p.y, x, e.x);                    // B*x + E
        float gx = fmaf(fmaf(p.x, x, p.w), x, e.y);      // (A*x + D)*x + F
        float q0 = fmaf(fmaf(p.z, y0, hx), y0, gx);
        float q1 = fmaf(fmaf(p.z, y1, hx), y1, gx);
        float a0 = ex2(q0);                              // = op * exp(-q/2)
        float a1 = ex2(q1);
        acc0 = fmaf(a0, T0, acc0); T0 = fmaf(-a0, T0, T0);
        acc1 = fmaf(a1, T1, acc1); T1 = fmaf(-a1, T1, T1);
    }

    const int z = blockIdx.z;
    const int pix0 = py0 * IMG_W + px;
    const int pix1 = pix0 + 8 * IMG_W;
    g_part[pix0 * NCHUNK + z] = make_float2(acc0, T0);
    g_part[pix1 * NCHUNK + z] = make_float2(acc1, T1);

    // ---- Last-arriving chunk-CTA of this tile combines (cheap handshake) ----
    const int tile = blockIdx.y * NTX + blockIdx.x;
    __syncthreads();   // all partial stores issued CTA-wide before tid0 releases
    if (tid == 0) {
        int prev;
        asm volatile("atom.acq_rel.gpu.global.add.s32 %0, [%1], 1;"
                     : "=r"(prev) : "l"(&g_cnt[tile]) : "memory");
        s_last = (prev == NCHUNK - 1);
    }
    __syncthreads();

    if (s_last) {
        const float4* g4 = (const float4*)g_part;
        #pragma unroll
        for (int k = 0; k < 2; ++k) {
            int pix = k ? pix1 : pix0;
            float4 u0 = __ldcg(&g4[pix * 4 + 0]);   // chunks 0,1
            float4 u1 = __ldcg(&g4[pix * 4 + 1]);   // chunks 2,3
            float4 u2 = __ldcg(&g4[pix * 4 + 2]);   // chunks 4,5
            float4 u3 = __ldcg(&g4[pix * 4 + 3]);   // chunks 6,7
            float r = fmaf(u3.y, u3.z, u3.x);       // a6 + T6*a7
            r = fmaf(u2.w, r, u2.z);
            r = fmaf(u2.y, r, u2.x);
            r = fmaf(u1.w, r, u1.z);
            r = fmaf(u1.y, r, u1.x);
            r = fmaf(u0.w, r, u0.z);
            r = fmaf(u0.y, r, u0.x);
            int o = pix * 3;
            out[o + 0] = r;
            out[o + 1] = r;
            out[o + 2] = r;     // BG = 0, all channels equal
        }
        if (tid == 0) atomicExch(&g_cnt[tile], 0);   // reset for next replay
    }
}

extern "C" void kernel_launch(void* const* d_in, const int* in_sizes, int n_in,
                              void* d_out, int out_size) {
    const float* means     = (const float*)d_in[0];
    const float* scales    = (const float*)d_in[1];
    const float* thetas    = (const float*)d_in[2];
    const float* opacities = (const float*)d_in[3];
    float* out = (float*)d_out;

    prep_kernel<<<NG / 64, 64>>>(means, scales, thetas, opacities);
    render_kernel<<<dim3(NTX, NTY, NCHUNK), dim3(16, 8)>>>(out);
}